// round 16
// baseline (speedup 1.0000x reference)
#include <cuda_runtime.h>
#include <cuda_fp16.h>
#include <cstdint>
#include <math.h>

// Problem dims
#define B_    32
#define E_    64
#define R_    36
#define D_    512
#define DT_   768
#define DI_   2048
#define TROWS 2048
#define IROWS 1152
#define IROWS_P 1280
#define SHI_S 516
#define ET    8
#define NCTA  144

// ---------------- scratch (device globals; .bss zero-initialized) ----------------
__device__ __align__(128) float g_T  [TROWS*D_];
__device__ __align__(128) float g_T2 [TROWS*D_];
__device__ __align__(128) float g_I  [IROWS_P*D_];
__device__ __align__(128) float g_I2 [IROWS_P*D_];
__device__ __align__(128) float g_I3 [IROWS_P*D_];
__device__ __align__(128) float g_I4 [IROWS_P*D_];
__device__ __align__(128) float g_HT [TROWS*D_];
__device__ __align__(128) float g_HT2[TROWS*D_];
__device__ __align__(128) float g_HI [IROWS_P*D_];
__device__ __align__(128) float g_HI2[IROWS_P*D_];
__device__ __align__(128) float g_tep[8*TROWS];
__device__ __align__(128) float g_urp[8*IROWS_P];
__device__ int g_cnt[B_];
__device__ int g_bar_count;
__device__ int g_bar_gen;

__device__ __align__(128) __half g_At [TROWS*DT_];
__device__ __align__(128) __half g_Ai [IROWS_P*DI_];
__device__ __align__(128) __half g_AT2[TROWS*D_];
__device__ __align__(128) __half g_AI2[IROWS_P*D_];
__device__ __align__(128) __half g_Bt [D_*DT_];
__device__ __align__(128) __half g_Bi [D_*DI_];
__device__ __align__(128) __half g_B1t[D_*D_];
__device__ __align__(128) __half g_B1i[D_*D_];

// ---------------- helpers ----------------
static __device__ __forceinline__ uint32_t smem_to_u32(const void* p){
    uint32_t a;
    asm("{ .reg .u64 t; cvta.to.shared.u64 t, %1; cvt.u32.u64 %0, t; }" : "=r"(a) : "l"(p));
    return a;
}

#define CP_ASYNC16(smad, gptr) \
    asm volatile("cp.async.ca.shared.global [%0], [%1], 16;" :: "r"(smad), "l"(gptr))
#define CP_COMMIT() asm volatile("cp.async.commit_group;" ::: "memory")
#define CP_WAIT3()  asm volatile("cp.async.wait_group 3;" ::: "memory")

#define LDSM_X4(r0,r1,r2,r3, addr) \
    asm volatile("ldmatrix.sync.aligned.m8n8.x4.shared.b16 {%0,%1,%2,%3}, [%4];" \
        : "=r"(r0), "=r"(r1), "=r"(r2), "=r"(r3) : "r"(addr))

static __device__ __forceinline__ void mma16816(float* c, const uint32_t* a, const uint32_t* b){
    asm volatile(
        "mma.sync.aligned.m16n8k16.row.col.f32.f16.f16.f32 "
        "{%0,%1,%2,%3}, {%4,%5,%6,%7}, {%8,%9}, {%0,%1,%2,%3};"
        : "+f"(c[0]), "+f"(c[1]), "+f"(c[2]), "+f"(c[3])
        : "r"(a[0]), "r"(a[1]), "r"(a[2]), "r"(a[3]), "r"(b[0]), "r"(b[1]));
}

static __device__ __forceinline__ unsigned long long f2add(unsigned long long a, unsigned long long b){
    unsigned long long r; asm("add.rn.f32x2 %0, %1, %2;" : "=l"(r) : "l"(a), "l"(b)); return r;
}
static __device__ __forceinline__ unsigned long long f2fma(unsigned long long a, unsigned long long b, unsigned long long c){
    unsigned long long r; asm("fma.rn.f32x2 %0, %1, %2, %3;" : "=l"(r) : "l"(a), "l"(b), "l"(c)); return r;
}
static __device__ __forceinline__ float2 upk2(unsigned long long v){
    float2 f; asm("mov.b64 {%0, %1}, %2;" : "=f"(f.x), "=f"(f.y) : "l"(v)); return f;
}

// grid-wide barrier (all CTAs resident: 144 CTAs @ 120KB smem = 1/SM, single wave)
static __device__ __forceinline__ void grid_sync(){
    __syncthreads();
    __threadfence();
    if (threadIdx.x == 0) {
        int gen = atomicAdd(&g_bar_gen, 0);
        __threadfence();
        if (atomicAdd(&g_bar_count, 1) == NCTA - 1) {
            atomicExch(&g_bar_count, 0);
            __threadfence();
            atomicAdd(&g_bar_gen, 1);
        } else {
            while (atomicAdd(&g_bar_gen, 0) == gen) { __nanosleep(64); }
        }
    }
    __syncthreads();
}

// ---------------- job descriptors ----------------
struct Job {
    const __half* A;
    const __half* B;
    const float* bias;
    float* C;
    const float* w2;
    float* dotp;
    int lda, ldb;
    int aoff;
    int NC;
    int mrows;
    int relu, hasbias;
};
struct JobPack { Job j[6]; int hi[6]; };

struct AllP {
    JobPack pa, pb;
    const float *W_text, *W_img, *W1, *text, *image;
    const float *gt, *bt, *gi, *bi;
    const float *W2, *b2;
    float* out;
};

#define ROWB    80
#define TILE_A  20480
#define STAGE_B 30720
#define STAGES  4
#define SM_TOT  (STAGES*STAGE_B)   // 122880

// ---------------- GEMM tile (R15-proven body) ----------------
static __device__ void run_gemm_tile(const Job jb, int rb, char* sm, uint32_t smb)
{
    const int tid = threadIdx.x;
    const int wid = tid >> 5, lane = tid & 31;
    const int m0 = (rb >> 2) * 256, n0 = (rb & 3) * 128;
    const int lda = jb.lda, ldb = jb.ldb, NC = jb.NC, aoff = jb.aoff;

    const int wm = (wid >> 2) * 64;
    const int wn = (wid & 3) * 32;
    const int cRow = tid >> 2, cCol = tid & 3;

    float acc[4][4][4];
    #pragma unroll
    for (int i = 0; i < 4; ++i)
        #pragma unroll
        for (int j = 0; j < 4; ++j)
            #pragma unroll
            for (int q = 0; q < 4; ++q) acc[i][j][q] = 0.f;

    const __half* gAb  = jb.A + (size_t)(m0 + cRow) * lda + aoff + cCol * 8;
    const __half* gAb2 = jb.A + (size_t)(m0 + cRow + 128) * lda + aoff + cCol * 8;
    const __half* gBb  = jb.B + (size_t)(n0 + cRow) * ldb + aoff + cCol * 8;
    const uint32_t sOffA  = (uint32_t)cRow * ROWB + cCol * 16;
    const uint32_t sOffA2 = (uint32_t)(cRow + 128) * ROWB + cCol * 16;
    const uint32_t sOffB  = TILE_A + (uint32_t)cRow * ROWB + cCol * 16;

    auto issue = [&](int chunk){
        if (chunk < NC) {
            const uint32_t sS = smb + (chunk & (STAGES-1)) * STAGE_B;
            const size_t ko = (size_t)chunk * 32;
            CP_ASYNC16(sS + sOffA,  gAb  + ko);
            CP_ASYNC16(sS + sOffA2, gAb2 + ko);
            CP_ASYNC16(sS + sOffB,  gBb  + ko);
        }
        CP_COMMIT();
    };

    issue(0); issue(1); issue(2);

    const uint32_t aFragOff = (uint32_t)(wm + (lane & 15)) * ROWB + ((lane >> 4) * 16);
    const uint32_t bFragOff = TILE_A
                              + (uint32_t)(wn + (lane & 7) + ((lane >> 4) << 3)) * ROWB
                              + (((lane >> 3) & 1) * 16);

    for (int c = 0; c < NC; ++c) {
        issue(c + 3);
        CP_WAIT3();
        __syncthreads();

        const uint32_t sS = smb + (c & (STAGES-1)) * STAGE_B;
        const uint32_t aBase = sS + aFragOff;
        const uint32_t bBase = sS + bFragOff;

        #pragma unroll
        for (int ks = 0; ks < 2; ++ks) {
            const uint32_t ko = ks * 32;
            uint32_t af[4][4];
            #pragma unroll
            for (int ma = 0; ma < 4; ++ma)
                LDSM_X4(af[ma][0], af[ma][1], af[ma][2], af[ma][3],
                        aBase + ma * (16 * ROWB) + ko);
            uint32_t bf[4][2];
            #pragma unroll
            for (int p = 0; p < 2; ++p) {
                uint32_t r0, r1, r2, r3;
                LDSM_X4(r0, r1, r2, r3, bBase + p * (16 * ROWB) + ko);
                bf[2*p][0] = r0; bf[2*p][1] = r1;
                bf[2*p+1][0] = r2; bf[2*p+1][1] = r3;
            }
            #pragma unroll
            for (int ma = 0; ma < 4; ++ma)
                #pragma unroll
                for (int na = 0; na < 4; ++na)
                    mma16816(acc[ma][na], af[ma], bf[na]);
        }
        __syncthreads();
    }

    const int relu = jb.relu;
    float dot0[4] = {0.f,0.f,0.f,0.f}, dot1[4] = {0.f,0.f,0.f,0.f};
    #pragma unroll
    for (int na = 0; na < 4; ++na) {
        const int col = n0 + wn + na * 8 + (lane & 3) * 2;
        float2 bv = make_float2(0.f, 0.f);
        if (jb.hasbias) bv = *reinterpret_cast<const float2*>(jb.bias + col);
        float2 wv = make_float2(0.f, 0.f);
        if (jb.w2) wv = *reinterpret_cast<const float2*>(jb.w2 + col);
        #pragma unroll
        for (int ma = 0; ma < 4; ++ma) {
            const int row = m0 + wm + ma * 16 + (lane >> 2);
            float2 o0, o1;
            o0.x = acc[ma][na][0] + bv.x; o0.y = acc[ma][na][1] + bv.y;
            o1.x = acc[ma][na][2] + bv.x; o1.y = acc[ma][na][3] + bv.y;
            if (relu) {
                o0.x = fmaxf(o0.x, 0.f); o0.y = fmaxf(o0.y, 0.f);
                o1.x = fmaxf(o1.x, 0.f); o1.y = fmaxf(o1.y, 0.f);
            }
            *reinterpret_cast<float2*>(jb.C + (size_t)row * 512 + col)       = o0;
            *reinterpret_cast<float2*>(jb.C + (size_t)(row + 8) * 512 + col) = o1;
            dot0[ma] += o0.x * wv.x + o0.y * wv.y;
            dot1[ma] += o1.x * wv.x + o1.y * wv.y;
        }
    }

    if (jb.w2) {
        __syncthreads();
        float* sf = reinterpret_cast<float*>(sm);
        #pragma unroll
        for (int ma = 0; ma < 4; ++ma) {
            float v0 = dot0[ma];
            v0 += __shfl_xor_sync(0xffffffffu, v0, 1);
            v0 += __shfl_xor_sync(0xffffffffu, v0, 2);
            float v1 = dot1[ma];
            v1 += __shfl_xor_sync(0xffffffffu, v1, 1);
            v1 += __shfl_xor_sync(0xffffffffu, v1, 2);
            if ((lane & 3) == 0) {
                int lr = wm + ma * 16 + (lane >> 2);
                sf[lr * 4 + (wid & 3)] = v0;
                sf[(lr + 8) * 4 + (wid & 3)] = v1;
            }
        }
        __syncthreads();
        if (tid < 256) {
            float s = sf[tid*4] + sf[tid*4+1] + sf[tid*4+2] + sf[tid*4+3];
            jb.dotp[(size_t)(n0 >> 7) * jb.mrows + m0 + tid] = s;
        }
        __syncthreads();
    }
}

// score smem layout (stride 288 for RED)
#define OFF_HI  0
#define OFF_HT  (R_ * SHI_S)                  // 18576
#define OFF_W2  (OFF_HT + ET * D_)            // 22672
#define OFF_RED (OFF_W2 + D_)                 // 23184
#define OFF_UR  (OFF_RED + ET * 288)          // 25488
#define OFF_TE  (OFF_UR + R_)                 // 25524

// ---------------- the one persistent kernel ----------------
__global__ __launch_bounds__(512, 1) void fused_all(AllP P)
{
    extern __shared__ __align__(128) char sm[];
    const uint32_t smb = smem_to_u32(sm);
    const int tid = threadIdx.x;
    const int bx = (int)blockIdx.x;

    // ===== phase 0: conversions (5760 items of 256 threads; 2 per CTA-iter) =====
    {
        const int t2 = tid & 255;
        const int half = tid >> 8;
        float* tb = reinterpret_cast<float*>(sm) + half * (32 * 33);
        for (int it = bx; it < 2880; it += NCTA) {
            int item = it * 2 + half;
            bool isT = item < 1920;
            if (isT) {
                const float* src; __half* dst; int K, idx;
                if      (item < 384)  { src = P.W_text;       dst = g_Bt;  K = DT_; idx = item; }
                else if (item < 1408) { src = P.W_img;        dst = g_Bi;  K = DI_; idx = item - 384; }
                else if (item < 1664) { src = P.W1;           dst = g_B1t; K = D_;  idx = item - 1408; }
                else                  { src = P.W1 + D_ * D_; dst = g_B1i; K = D_;  idx = item - 1664; }
                int kblocks = K / 32;
                int kb = (idx % kblocks) * 32, nb = (idx / kblocks) * 32;
                int tx = t2 & 31, ty = t2 >> 5;
                #pragma unroll
                for (int j = 0; j < 4; ++j)
                    tb[(ty + 8*j) * 33 + tx] = src[(size_t)(kb + ty + 8*j) * 512 + nb + tx];
                __syncthreads();
                int n  = nb + (t2 >> 3);
                int k4 = (t2 & 7) * 4;
                __half2 p0, p1;
                p0.x = __float2half_rn(tb[(k4 + 0) * 33 + (t2 >> 3)]);
                p0.y = __float2half_rn(tb[(k4 + 1) * 33 + (t2 >> 3)]);
                p1.x = __float2half_rn(tb[(k4 + 2) * 33 + (t2 >> 3)]);
                p1.y = __float2half_rn(tb[(k4 + 3) * 33 + (t2 >> 3)]);
                __half2* d2 = reinterpret_cast<__half2*>(dst + (size_t)n * K + kb + k4);
                d2[0] = p0; d2[1] = p1;
                __syncthreads();
            } else {
                int gi = (item - 1920) * 256 + t2;
                const int TQ = TROWS * DT_ / 4;
                const float4* src; __half* dst; int e4;
                if (gi < TQ) { src = reinterpret_cast<const float4*>(P.text);  dst = g_At; e4 = gi; }
                else         { src = reinterpret_cast<const float4*>(P.image); dst = g_Ai; e4 = gi - TQ; }
                float4 v = src[e4];
                __half2 p0, p1;
                p0.x = __float2half_rn(v.x); p0.y = __float2half_rn(v.y);
                p1.x = __float2half_rn(v.z); p1.y = __float2half_rn(v.w);
                __half2* d2 = reinterpret_cast<__half2*>(dst + (size_t)e4 * 4);
                d2[0] = p0; d2[1] = p1;
                __syncthreads();
                __syncthreads();
            }
        }
    }
    grid_sync();

    // ===== phase 1: projection GEMMs (144 tiles = 1 per CTA) =====
    {
        int jx = 0;
        #pragma unroll
        for (int k = 0; k < 5; ++k) jx += (bx >= P.pa.hi[k]);
        run_gemm_tile(P.pa.j[jx], bx - (jx ? P.pa.hi[jx-1] : 0), sm, smb);
    }
    grid_sync();

    // ===== phase 2: LN + relu-sum + fp16 convert (3200 rows, 4 per CTA-iter) =====
    {
        float* rsx = reinterpret_cast<float*>(sm);         // 16 floats
        float* rssx = rsx + 16;
        const int sub = tid >> 7;          // 0..3
        const int t = tid & 127;
        const int wl = (t >> 5);           // warp in sub 0..3
        const int l = t & 31;
        for (int rg = bx; rg < 800; rg += NCTA) {
            int gr = rg * 4 + sub;
            const float* g; const float* beta; __half* dst;
            int row; bool img;
            if (gr < TROWS) { row = gr;         g = P.gt; beta = P.bt; dst = g_AT2 + (size_t)row * D_; img = false; }
            else            { row = gr - TROWS; g = P.gi; beta = P.bi; dst = g_AI2 + (size_t)row * D_; img = true; }

            float4 v;
            if (!img) {
                float4 a = reinterpret_cast<const float4*>(g_T  + (size_t)row * D_)[t];
                float4 b = reinterpret_cast<const float4*>(g_T2 + (size_t)row * D_)[t];
                v.x = fmaxf(a.x + b.x, 0.f); v.y = fmaxf(a.y + b.y, 0.f);
                v.z = fmaxf(a.z + b.z, 0.f); v.w = fmaxf(a.w + b.w, 0.f);
            } else {
                float4 a = reinterpret_cast<const float4*>(g_I  + (size_t)row * D_)[t];
                float4 b = reinterpret_cast<const float4*>(g_I2 + (size_t)row * D_)[t];
                float4 c = reinterpret_cast<const float4*>(g_I3 + (size_t)row * D_)[t];
                float4 d = reinterpret_cast<const float4*>(g_I4 + (size_t)row * D_)[t];
                v.x = fmaxf(a.x + b.x + c.x + d.x, 0.f); v.y = fmaxf(a.y + b.y + c.y + d.y, 0.f);
                v.z = fmaxf(a.z + b.z + c.z + d.z, 0.f); v.w = fmaxf(a.w + b.w + c.w + d.w, 0.f);
            }
            float s  = v.x + v.y + v.z + v.w;
            float ss = v.x * v.x + v.y * v.y + v.z * v.z + v.w * v.w;
            #pragma unroll
            for (int o = 16; o; o >>= 1) {
                s  += __shfl_xor_sync(0xffffffffu, s,  o);
                ss += __shfl_xor_sync(0xffffffffu, ss, o);
            }
            if (l == 0) { rsx[sub * 4 + wl] = s; rssx[sub * 4 + wl] = ss; }
            __syncthreads();
            s  = rsx[sub*4+0] + rsx[sub*4+1] + rsx[sub*4+2] + rsx[sub*4+3];
            ss = rssx[sub*4+0] + rssx[sub*4+1] + rssx[sub*4+2] + rssx[sub*4+3];
            float mu   = s * (1.f / D_);
            float var  = ss * (1.f / D_) - mu * mu;
            float rstd = rsqrtf(var + 1e-5f);
            float4 gg = reinterpret_cast<const float4*>(g)[t];
            float4 bb = reinterpret_cast<const float4*>(beta)[t];
            v.x = (v.x - mu) * rstd * gg.x + bb.x;
            v.y = (v.y - mu) * rstd * gg.y + bb.y;
            v.z = (v.z - mu) * rstd * gg.z + bb.z;
            v.w = (v.w - mu) * rstd * gg.w + bb.w;
            if (img) reinterpret_cast<float4*>(g_I + (size_t)row * D_)[t] = v;

            __half2 p01, p23;
            p01.x = __float2half_rn(v.x); p01.y = __float2half_rn(v.y);
            p23.x = __float2half_rn(v.z); p23.y = __float2half_rn(v.w);
            __half2* d2 = reinterpret_cast<__half2*>(dst);
            d2[t * 2] = p01;
            d2[t * 2 + 1] = p23;
            __syncthreads();
        }
    }
    grid_sync();

    // ===== phase 3: second-layer GEMMs (104 tiles over 144 CTAs) =====
    for (int tl = bx; tl < 104; tl += NCTA) {
        int jx = 0;
        #pragma unroll
        for (int k = 0; k < 5; ++k) jx += (tl >= P.pb.hi[k]);
        run_gemm_tile(P.pb.j[jx], tl - (jx ? P.pb.hi[jx-1] : 0), sm, smb);
    }
    grid_sync();

    // ===== phase 4: score + last-block softmax/agg (256 vblocks) =====
    {
        float* smf = reinterpret_cast<float*>(sm);
        float* out = P.out;
        for (int v = bx; v < 256; v += NCTA) {
            const int b = v >> 3, e0 = (v & 7) * ET;
            {
                const float4* src  = reinterpret_cast<const float4*>(g_HI  + (size_t)b * R_ * D_);
                const float4* src2 = reinterpret_cast<const float4*>(g_HI2 + (size_t)b * R_ * D_);
                for (int i = tid; i < R_ * (D_ / 4); i += 512) {
                    int row = i >> 7, c = i & 127;
                    float4 a = src[i], d = src2[i];
                    float4 o; o.x = a.x + d.x; o.y = a.y + d.y; o.z = a.z + d.z; o.w = a.w + d.w;
                    reinterpret_cast<float4*>(smf + OFF_HI + row * SHI_S)[c] = o;
                }
                const float4* srcT  = reinterpret_cast<const float4*>(g_HT  + (size_t)(b * E_ + e0) * D_);
                const float4* srcT2 = reinterpret_cast<const float4*>(g_HT2 + (size_t)(b * E_ + e0) * D_);
                for (int i = tid; i < ET * (D_ / 4); i += 512) {
                    float4 a = srcT[i], d = srcT2[i];
                    float4 o; o.x = a.x + d.x; o.y = a.y + d.y; o.z = a.z + d.z; o.w = a.w + d.w;
                    reinterpret_cast<float4*>(smf + OFF_HT)[i] = o;
                }
                const float4* srcW = reinterpret_cast<const float4*>(P.W2);
                for (int i = tid; i < D_ / 4; i += 512)
                    reinterpret_cast<float4*>(smf + OFF_W2)[i] = srcW[i];
                if (tid < R_) {
                    int r = b * R_ + tid;
                    float s = 0.f;
                    #pragma unroll
                    for (int k = 0; k < 8; ++k) s += g_urp[k * IROWS_P + r];
                    smf[OFF_UR + tid] = s;
                }
                if (tid < ET) {
                    int r = b * E_ + e0 + tid;
                    float s = 0.f;
                    #pragma unroll
                    for (int k = 0; k < 8; ++k) s += g_tep[k * TROWS + r];
                    smf[OFF_TE + tid] = s;
                }
            }
            __syncthreads();

            if (tid < 288) {
                int q8 = tid / 36;
                int r  = tid - q8 * 36;
                const ulonglong2* hp = reinterpret_cast<const ulonglong2*>(smf + OFF_HI + r * SHI_S + q8 * 64);
                const ulonglong2* wp = reinterpret_cast<const ulonglong2*>(smf + OFF_W2 + q8 * 64);
                const ulonglong2* tp = reinterpret_cast<const ulonglong2*>(smf + OFF_HT + q8 * 64);
                const unsigned long long ABSM = 0x7FFFFFFF7FFFFFFFull;
                unsigned long long ac[ET];
                #pragma unroll
                for (int e = 0; e < ET; ++e) ac[e] = 0;
                #pragma unroll 4
                for (int j = 0; j < 16; ++j) {
                    ulonglong2 h = hp[j];
                    ulonglong2 w = wp[j];
                    #pragma unroll
                    for (int e = 0; e < ET; ++e) {
                        ulonglong2 t = tp[e * 128 + j];
                        ac[e] = f2fma(f2add(t.x, h.x) & ABSM, w.x, ac[e]);
                        ac[e] = f2fma(f2add(t.y, h.y) & ABSM, w.y, ac[e]);
                    }
                }
                #pragma unroll
                for (int e = 0; e < ET; ++e) {
                    float2 p = upk2(ac[e]);
                    smf[OFF_RED + e * 288 + tid] = p.x + p.y;
                }
            }
            __syncthreads();

            if (tid < R_) {
                float b2v = P.b2[0];
                float ur  = smf[OFF_UR + tid];
                #pragma unroll
                for (int e = 0; e < ET; ++e) {
                    const float* rd = smf + OFF_RED + e * 288;
                    float S = 0.f;
                    #pragma unroll
                    for (int k = 0; k < 8; ++k) S += rd[k * 36 + tid];
                    float raw = 0.5f * (smf[OFF_TE + e] + ur + S) + b2v;
                    out[b * (E_ * R_) + (e0 + e) * R_ + tid] = 1.0f / (1.0f + expf(-raw));
                }
            }

            // last-block ticket for this batch
            __threadfence();
            __shared__ int ticket;
            __syncthreads();
            if (tid == 0) ticket = atomicAdd(&g_cnt[b], 1);
            __syncthreads();
            if (ticket == (E_ / ET) - 1) {
                if (tid == 0) g_cnt[b] = 0;

                float* s   = smf;
                float* red = smf + E_ * R_;
                float* wr  = red + 16;
                const int lane = tid & 31, w = tid >> 5;

                float mx = -1e30f;
                for (int i = tid; i < E_ * R_; i += 512) {
                    float x = out[b * E_ * R_ + i];
                    s[i] = x;
                    mx = fmaxf(mx, x);
                }
                #pragma unroll
                for (int o = 16; o; o >>= 1) mx = fmaxf(mx, __shfl_xor_sync(0xffffffffu, mx, o));
                if (lane == 0) red[w] = mx;
                __syncthreads();
                float m = red[0];
                #pragma unroll
                for (int k = 1; k < 16; ++k) m = fmaxf(m, red[k]);
                __syncthreads();

                float sum = 0.f;
                for (int i = tid; i < E_ * R_; i += 512) {
                    float e2 = expf(s[i] - m);
                    s[i] = e2;
                    sum += e2;
                }
                #pragma unroll
                for (int o = 16; o; o >>= 1) sum += __shfl_xor_sync(0xffffffffu, sum, o);
                if (lane == 0) red[w] = sum;
                __syncthreads();
                float Z = 0.f;
                #pragma unroll
                for (int k = 0; k < 16; ++k) Z += red[k];
                float scale = 1.0f / (Z * (float)E_);

                if (tid < R_) {
                    float a = 0.f;
                    for (int e = 0; e < E_; ++e) a += s[e * R_ + tid];
                    wr[tid] = a * scale;
                }
                __syncthreads();

                for (int d = tid; d < D_; d += 512) {
                    float a = 0.f;
                    #pragma unroll
                    for (int r2 = 0; r2 < R_; ++r2)
                        a += wr[r2] * g_I[(size_t)(b * R_ + r2) * D_ + d];
                    out[B_ * E_ * R_ + b * D_ + d] = a;
                }
            }
            __syncthreads();
        }
    }
}

// ---------------- launch ----------------
extern "C" void kernel_launch(void* const* d_in, const int* in_sizes, int n_in,
                              void* d_out, int out_size)
{
    (void)in_sizes; (void)n_in; (void)out_size;
    AllP P;
    P.W_text = (const float*)d_in[2];
    P.text   = (const float*)d_in[0];
    P.image  = (const float*)d_in[1];
    const float* b_text = (const float*)d_in[3];
    P.gt = (const float*)d_in[4];
    P.bt = (const float*)d_in[5];
    P.W_img = (const float*)d_in[6];
    const float* b_img = (const float*)d_in[7];
    P.gi = (const float*)d_in[8];
    P.bi = (const float*)d_in[9];
    P.W1 = (const float*)d_in[10];
    const float* b1 = (const float*)d_in[11];
    P.W2 = (const float*)d_in[12];
    P.b2 = (const float*)d_in[13];
    P.out = (float*)d_out;

    void* p;
    cudaGetSymbolAddress(&p, g_T);   float* T   = (float*)p;
    cudaGetSymbolAddress(&p, g_T2);  float* T2  = (float*)p;
    cudaGetSymbolAddress(&p, g_I);   float* I   = (float*)p;
    cudaGetSymbolAddress(&p, g_I2);  float* I2  = (float*)p;
    cudaGetSymbolAddress(&p, g_I3);  float* I3  = (float*)p;
    cudaGetSymbolAddress(&p, g_I4);  float* I4  = (float*)p;
    cudaGetSymbolAddress(&p, g_HT);  float* HT  = (float*)p;
    cudaGetSymbolAddress(&p, g_HT2); float* HT2 = (float*)p;
    cudaGetSymbolAddress(&p, g_HI);  float* HI  = (float*)p;
    cudaGetSymbolAddress(&p, g_HI2); float* HI2 = (float*)p;
    cudaGetSymbolAddress(&p, g_tep); float* tep = (float*)p;
    cudaGetSymbolAddress(&p, g_urp); float* urp = (float*)p;
    cudaGetSymbolAddress(&p, g_At);  __half* At  = (__half*)p;
    cudaGetSymbolAddress(&p, g_Ai);  __half* Ai  = (__half*)p;
    cudaGetSymbolAddress(&p, g_AT2); __half* AT2 = (__half*)p;
    cudaGetSymbolAddress(&p, g_AI2); __half* AI2 = (__half*)p;
    cudaGetSymbolAddress(&p, g_Bt);  __half* Bt  = (__half*)p;
    cudaGetSymbolAddress(&p, g_Bi);  __half* Bi  = (__half*)p;
    cudaGetSymbolAddress(&p, g_B1t); __half* B1t = (__half*)p;
    cudaGetSymbolAddress(&p, g_B1i); __half* B1i = (__half*)p;

    // phase A jobs
    P.pa.j[0] = { At, Bt, b_text,  T,  nullptr, nullptr, DT_, DT_, 0,    384/32, TROWS,   0, 1 };
    P.pa.j[1] = { At, Bt, nullptr, T2, nullptr, nullptr, DT_, DT_, 384,  384/32, TROWS,   0, 0 };
    P.pa.j[2] = { Ai, Bi, b_img,   I,  nullptr, nullptr, DI_, DI_, 0,    512/32, IROWS_P, 0, 1 };
    P.pa.j[3] = { Ai, Bi, nullptr, I2, nullptr, nullptr, DI_, DI_, 512,  512/32, IROWS_P, 0, 0 };
    P.pa.j[4] = { Ai, Bi, nullptr, I3, nullptr, nullptr, DI_, DI_, 1024, 512/32, IROWS_P, 0, 0 };
    P.pa.j[5] = { Ai, Bi, nullptr, I4, nullptr, nullptr, DI_, DI_, 1536, 512/32, IROWS_P, 0, 0 };
    P.pa.hi[0] = 32; P.pa.hi[1] = 64; P.pa.hi[2] = 84; P.pa.hi[3] = 104; P.pa.hi[4] = 124; P.pa.hi[5] = 144;

    // phase B jobs
    P.pb.j[0] = { AT2, B1t, nullptr, HT,  P.W2, tep,             D_, D_, 0,   256/32, TROWS,   0, 0 };
    P.pb.j[1] = { AT2, B1t, nullptr, HT2, P.W2, tep + 4*TROWS,   D_, D_, 256, 256/32, TROWS,   0, 0 };
    P.pb.j[2] = { AI2, B1i, b1,      HI,  P.W2, urp,             D_, D_, 0,   256/32, IROWS_P, 0, 1 };
    P.pb.j[3] = { AI2, B1i, nullptr, HI2, P.W2, urp + 4*IROWS_P, D_, D_, 256, 256/32, IROWS_P, 0, 0 };
    P.pb.j[4] = P.pb.j[3]; P.pb.j[5] = P.pb.j[3];
    P.pb.hi[0] = 32; P.pb.hi[1] = 64; P.pb.hi[2] = 84; P.pb.hi[3] = 104; P.pb.hi[4] = 104; P.pb.hi[5] = 104;

    cudaFuncSetAttribute(fused_all, cudaFuncAttributeMaxDynamicSharedMemorySize, SM_TOT);
    fused_all<<<NCTA, 512, SM_TOT>>>(P);
}

// round 17
// speedup vs baseline: 1.1866x; 1.1866x over previous
#include <cuda_runtime.h>
#include <cuda_fp16.h>
#include <cstdint>
#include <math.h>

// Problem dims
#define B_    32
#define E_    64
#define R_    36
#define D_    512
#define DT_   768
#define DI_   2048
#define TROWS 2048   // B*E
#define IROWS 1152   // B*R
#define IROWS_P 1280 // padded to multiple of 256 for BM=256
#define SHI_S 516
#define ET    8      // e-tile in score kernel
#define STH   320    // score kernel threads

// ---------------- scratch (device globals; .bss zero-initialized) ----------------
__device__ __align__(128) float g_T  [TROWS*D_];
__device__ __align__(128) float g_T2 [TROWS*D_];
__device__ __align__(128) float g_I  [IROWS_P*D_];
__device__ __align__(128) float g_I2 [IROWS_P*D_];
__device__ __align__(128) float g_I3 [IROWS_P*D_];
__device__ __align__(128) float g_I4 [IROWS_P*D_];
__device__ __align__(128) float g_HT [TROWS*D_];
__device__ __align__(128) float g_HT2[TROWS*D_];
__device__ __align__(128) float g_HI [IROWS_P*D_];
__device__ __align__(128) float g_HI2[IROWS_P*D_];
__device__ __align__(128) float g_tep[8*TROWS];
__device__ __align__(128) float g_urp[8*IROWS_P];
__device__ int g_cnt[B_];   // per-batch ticket; self-resetting

__device__ __align__(128) __half g_At [TROWS*DT_];
__device__ __align__(128) __half g_Ai [IROWS_P*DI_];    // rows >=1152 stay zero
__device__ __align__(128) __half g_AT2[TROWS*D_];
__device__ __align__(128) __half g_AI2[IROWS_P*D_];     // rows >=1152 stay zero
__device__ __align__(128) __half g_Bt [D_*DT_];
__device__ __align__(128) __half g_Bi [D_*DI_];
__device__ __align__(128) __half g_B1t[D_*D_];
__device__ __align__(128) __half g_B1i[D_*D_];

// ---------------- helpers ----------------
static __device__ __forceinline__ uint32_t smem_to_u32(const void* p){
    uint32_t a;
    asm("{ .reg .u64 t; cvta.to.shared.u64 t, %1; cvt.u32.u64 %0, t; }" : "=r"(a) : "l"(p));
    return a;
}

// PDL: wait for all upstream grids' memory to be visible
static __device__ __forceinline__ void pdl_wait(){
#if defined(__CUDA_ARCH__) && (__CUDA_ARCH__ >= 900)
    cudaGridDependencySynchronize();
#endif
}

#define CP_ASYNC16(smad, gptr) \
    asm volatile("cp.async.ca.shared.global [%0], [%1], 16;" :: "r"(smad), "l"(gptr))
#define CP_COMMIT() asm volatile("cp.async.commit_group;" ::: "memory")
#define CP_WAIT3()  asm volatile("cp.async.wait_group 3;" ::: "memory")

#define LDSM_X4(r0,r1,r2,r3, addr) \
    asm volatile("ldmatrix.sync.aligned.m8n8.x4.shared.b16 {%0,%1,%2,%3}, [%4];" \
        : "=r"(r0), "=r"(r1), "=r"(r2), "=r"(r3) : "r"(addr))

static __device__ __forceinline__ void mma16816(float* c, const uint32_t* a, const uint32_t* b){
    asm volatile(
        "mma.sync.aligned.m16n8k16.row.col.f32.f16.f16.f32 "
        "{%0,%1,%2,%3}, {%4,%5,%6,%7}, {%8,%9}, {%0,%1,%2,%3};"
        : "+f"(c[0]), "+f"(c[1]), "+f"(c[2]), "+f"(c[3])
        : "r"(a[0]), "r"(a[1]), "r"(a[2]), "r"(a[3]), "r"(b[0]), "r"(b[1]));
}

// ---------------- merged conversion kernel (vectorized) ----------------
__global__ __launch_bounds__(256) void conv_all_k(const float* __restrict__ W_text,
                                                  const float* __restrict__ W_img,
                                                  const float* __restrict__ W1,
                                                  const float* __restrict__ text,
                                                  const float* __restrict__ image)
{
    __shared__ float t[32][33];
    int bx = blockIdx.x;
    int tid = threadIdx.x;
    if (bx < 1920) {
        const float* src; __half* dst; int K, idx;
        if      (bx < 384)  { src = W_text;       dst = g_Bt;  K = DT_; idx = bx; }
        else if (bx < 1408) { src = W_img;        dst = g_Bi;  K = DI_; idx = bx - 384; }
        else if (bx < 1664) { src = W1;           dst = g_B1t; K = D_;  idx = bx - 1408; }
        else                { src = W1 + D_ * D_; dst = g_B1i; K = D_;  idx = bx - 1664; }
        int kblocks = K / 32;
        int kb = (idx % kblocks) * 32, nb = (idx / kblocks) * 32;
        int tx = tid & 31, ty = tid >> 5;
        #pragma unroll
        for (int j = 0; j < 4; ++j)
            t[ty + 8*j][tx] = src[(size_t)(kb + ty + 8*j) * 512 + nb + tx];
        __syncthreads();
        int n  = nb + (tid >> 3);
        int k4 = (tid & 7) * 4;
        __half2 p0, p1;
        p0.x = __float2half_rn(t[k4 + 0][tid >> 3]);
        p0.y = __float2half_rn(t[k4 + 1][tid >> 3]);
        p1.x = __float2half_rn(t[k4 + 2][tid >> 3]);
        p1.y = __float2half_rn(t[k4 + 3][tid >> 3]);
        __half2* d2 = reinterpret_cast<__half2*>(dst + (size_t)n * K + kb + k4);
        d2[0] = p0; d2[1] = p1;
    } else {
        int gi = (bx - 1920) * 256 + tid;               // float4 index
        const int TQ = TROWS * DT_ / 4;
        const float4* src; __half* dst; int e4;
        if (gi < TQ) { src = reinterpret_cast<const float4*>(text);  dst = g_At; e4 = gi; }
        else         { src = reinterpret_cast<const float4*>(image); dst = g_Ai; e4 = gi - TQ; }
        float4 v = src[e4];
        __half2 p0, p1;
        p0.x = __float2half_rn(v.x); p0.y = __float2half_rn(v.y);
        p1.x = __float2half_rn(v.z); p1.y = __float2half_rn(v.w);
        __half2* d2 = reinterpret_cast<__half2*>(dst + (size_t)e4 * 4);
        d2[0] = p0; d2[1] = p1;
    }
}

// ---------------- mma.sync GEMM: BM=256, BN=128, BK=32, 512 threads, 4-stage cp.async ----------------
struct Job {
    const __half* A;
    const __half* B;
    const float* bias;
    float* C;
    const float* w2;
    float* dotp;
    int lda, ldb;
    int aoff;
    int NC;
    int mrows;
    int relu, hasbias;
};
struct JobPack { Job j[6]; int hi[6]; };

#define ROWB    80
#define TILE_A  20480
#define STAGE_B 30720
#define STAGES  4
#define SM_TOT  (STAGES*STAGE_B)   // 122880

__global__ __launch_bounds__(512, 1) void mma_gemm3(JobPack P)
{
    extern __shared__ __align__(128) char sm[];
    const uint32_t smb = smem_to_u32(sm);
    const int tid = threadIdx.x;
    const int wid = tid >> 5, lane = tid & 31;

    int bx = (int)blockIdx.x;
    int jx = 0;
    #pragma unroll
    for (int k = 0; k < 5; ++k) jx += (bx >= P.hi[k]);
    Job jb = P.j[jx];
    int rb = bx - (jx ? P.hi[jx-1] : 0);

    const int m0 = (rb >> 2) * 256, n0 = (rb & 3) * 128;
    const int lda = jb.lda, ldb = jb.ldb, NC = jb.NC, aoff = jb.aoff;

    const int wm = (wid >> 2) * 64;
    const int wn = (wid & 3) * 32;

    const int cRow = tid >> 2, cCol = tid & 3;

    float acc[4][4][4];
    #pragma unroll
    for (int i = 0; i < 4; ++i)
        #pragma unroll
        for (int j = 0; j < 4; ++j)
            #pragma unroll
            for (int q = 0; q < 4; ++q) acc[i][j][q] = 0.f;

    const __half* gAb  = jb.A + (size_t)(m0 + cRow) * lda + aoff + cCol * 8;
    const __half* gAb2 = jb.A + (size_t)(m0 + cRow + 128) * lda + aoff + cCol * 8;
    const __half* gBb  = jb.B + (size_t)(n0 + cRow) * ldb + aoff + cCol * 8;
    const uint32_t sOffA  = (uint32_t)cRow * ROWB + cCol * 16;
    const uint32_t sOffA2 = (uint32_t)(cRow + 128) * ROWB + cCol * 16;
    const uint32_t sOffB  = TILE_A + (uint32_t)cRow * ROWB + cCol * 16;

    auto issue = [&](int chunk){
        if (chunk < NC) {
            const uint32_t sS = smb + (chunk & (STAGES-1)) * STAGE_B;
            const size_t ko = (size_t)chunk * 32;
            CP_ASYNC16(sS + sOffA,  gAb  + ko);
            CP_ASYNC16(sS + sOffA2, gAb2 + ko);
            CP_ASYNC16(sS + sOffB,  gBb  + ko);
        }
        CP_COMMIT();
    };

    // wait for upstream grid's writes before first dependent read
    pdl_wait();

    issue(0); issue(1); issue(2);

    const uint32_t aFragOff = (uint32_t)(wm + (lane & 15)) * ROWB + ((lane >> 4) * 16);
    const uint32_t bFragOff = TILE_A
                              + (uint32_t)(wn + (lane & 7) + ((lane >> 4) << 3)) * ROWB
                              + (((lane >> 3) & 1) * 16);

    for (int c = 0; c < NC; ++c) {
        issue(c + 3);
        CP_WAIT3();
        __syncthreads();

        const uint32_t sS = smb + (c & (STAGES-1)) * STAGE_B;
        const uint32_t aBase = sS + aFragOff;
        const uint32_t bBase = sS + bFragOff;

        #pragma unroll
        for (int ks = 0; ks < 2; ++ks) {
            const uint32_t ko = ks * 32;
            uint32_t af[4][4];
            #pragma unroll
            for (int ma = 0; ma < 4; ++ma)
                LDSM_X4(af[ma][0], af[ma][1], af[ma][2], af[ma][3],
                        aBase + ma * (16 * ROWB) + ko);
            uint32_t bf[4][2];
            #pragma unroll
            for (int p = 0; p < 2; ++p) {
                uint32_t r0, r1, r2, r3;
                LDSM_X4(r0, r1, r2, r3, bBase + p * (16 * ROWB) + ko);
                bf[2*p][0] = r0; bf[2*p][1] = r1;
                bf[2*p+1][0] = r2; bf[2*p+1][1] = r3;
            }
            #pragma unroll
            for (int ma = 0; ma < 4; ++ma)
                #pragma unroll
                for (int na = 0; na < 4; ++na)
                    mma16816(acc[ma][na], af[ma], bf[na]);
        }
        __syncthreads();
    }

    const int relu = jb.relu;
    float dot0[4] = {0.f,0.f,0.f,0.f}, dot1[4] = {0.f,0.f,0.f,0.f};
    #pragma unroll
    for (int na = 0; na < 4; ++na) {
        const int col = n0 + wn + na * 8 + (lane & 3) * 2;
        float2 bv = make_float2(0.f, 0.f);
        if (jb.hasbias) bv = *reinterpret_cast<const float2*>(jb.bias + col);
        float2 wv = make_float2(0.f, 0.f);
        if (jb.w2) wv = *reinterpret_cast<const float2*>(jb.w2 + col);
        #pragma unroll
        for (int ma = 0; ma < 4; ++ma) {
            const int row = m0 + wm + ma * 16 + (lane >> 2);
            float2 o0, o1;
            o0.x = acc[ma][na][0] + bv.x; o0.y = acc[ma][na][1] + bv.y;
            o1.x = acc[ma][na][2] + bv.x; o1.y = acc[ma][na][3] + bv.y;
            if (relu) {
                o0.x = fmaxf(o0.x, 0.f); o0.y = fmaxf(o0.y, 0.f);
                o1.x = fmaxf(o1.x, 0.f); o1.y = fmaxf(o1.y, 0.f);
            }
            *reinterpret_cast<float2*>(jb.C + (size_t)row * 512 + col)       = o0;
            *reinterpret_cast<float2*>(jb.C + (size_t)(row + 8) * 512 + col) = o1;
            dot0[ma] += o0.x * wv.x + o0.y * wv.y;
            dot1[ma] += o1.x * wv.x + o1.y * wv.y;
        }
    }

    if (jb.w2) {
        __syncthreads();
        float* sf = reinterpret_cast<float*>(sm);
        #pragma unroll
        for (int ma = 0; ma < 4; ++ma) {
            float v0 = dot0[ma];
            v0 += __shfl_xor_sync(0xffffffffu, v0, 1);
            v0 += __shfl_xor_sync(0xffffffffu, v0, 2);
            float v1 = dot1[ma];
            v1 += __shfl_xor_sync(0xffffffffu, v1, 1);
            v1 += __shfl_xor_sync(0xffffffffu, v1, 2);
            if ((lane & 3) == 0) {
                int lr = wm + ma * 16 + (lane >> 2);
                sf[lr * 4 + (wid & 3)] = v0;
                sf[(lr + 8) * 4 + (wid & 3)] = v1;
            }
        }
        __syncthreads();
        if (tid < 256) {
            float s = sf[tid*4] + sf[tid*4+1] + sf[tid*4+2] + sf[tid*4+3];
            jb.dotp[(size_t)(n0 >> 7) * jb.mrows + m0 + tid] = s;
        }
    }
}

// ---------------- merged LN: sum split-K partials + relu + LN + fp16 convert ----------------
__global__ __launch_bounds__(128) void ln_all_k(const float* __restrict__ gt,
                                                const float* __restrict__ bt,
                                                const float* __restrict__ gi,
                                                const float* __restrict__ bi)
{
    const int bx = blockIdx.x, tid = threadIdx.x;
    const float* g; const float* beta; __half* dst;
    int row; bool img;
    if (bx < TROWS) { row = bx;         g = gt; beta = bt; dst = g_AT2 + (size_t)row * D_; img = false; }
    else            { row = bx - TROWS; g = gi; beta = bi; dst = g_AI2 + (size_t)row * D_; img = true; }

    pdl_wait();

    float4 v;
    if (!img) {
        float4 a = reinterpret_cast<const float4*>(g_T  + (size_t)row * D_)[tid];
        float4 b = reinterpret_cast<const float4*>(g_T2 + (size_t)row * D_)[tid];
        v.x = fmaxf(a.x + b.x, 0.f); v.y = fmaxf(a.y + b.y, 0.f);
        v.z = fmaxf(a.z + b.z, 0.f); v.w = fmaxf(a.w + b.w, 0.f);
    } else {
        float4 a = reinterpret_cast<const float4*>(g_I  + (size_t)row * D_)[tid];
        float4 b = reinterpret_cast<const float4*>(g_I2 + (size_t)row * D_)[tid];
        float4 c = reinterpret_cast<const float4*>(g_I3 + (size_t)row * D_)[tid];
        float4 d = reinterpret_cast<const float4*>(g_I4 + (size_t)row * D_)[tid];
        v.x = fmaxf(a.x + b.x + c.x + d.x, 0.f); v.y = fmaxf(a.y + b.y + c.y + d.y, 0.f);
        v.z = fmaxf(a.z + b.z + c.z + d.z, 0.f); v.w = fmaxf(a.w + b.w + c.w + d.w, 0.f);
    }
    float s  = v.x + v.y + v.z + v.w;
    float ss = v.x * v.x + v.y * v.y + v.z * v.z + v.w * v.w;
    #pragma unroll
    for (int o = 16; o; o >>= 1) {
        s  += __shfl_xor_sync(0xffffffffu, s,  o);
        ss += __shfl_xor_sync(0xffffffffu, ss, o);
    }
    __shared__ float rs[4], rss[4];
    int w = tid >> 5, l = tid & 31;
    if (l == 0) { rs[w] = s; rss[w] = ss; }
    __syncthreads();
    s  = rs[0] + rs[1] + rs[2] + rs[3];
    ss = rss[0] + rss[1] + rss[2] + rss[3];
    float mu   = s * (1.f / D_);
    float var  = ss * (1.f / D_) - mu * mu;
    float rstd = rsqrtf(var + 1e-5f);
    float4 gg = reinterpret_cast<const float4*>(g)[tid];
    float4 bb = reinterpret_cast<const float4*>(beta)[tid];
    v.x = (v.x - mu) * rstd * gg.x + bb.x;
    v.y = (v.y - mu) * rstd * gg.y + bb.y;
    v.z = (v.z - mu) * rstd * gg.z + bb.z;
    v.w = (v.w - mu) * rstd * gg.w + bb.w;
    if (img) reinterpret_cast<float4*>(g_I + (size_t)row * D_)[tid] = v;

    __half2 p01, p23;
    p01.x = __float2half_rn(v.x); p01.y = __float2half_rn(v.y);
    p23.x = __float2half_rn(v.z); p23.y = __float2half_rn(v.w);
    __half2* d2 = reinterpret_cast<__half2*>(dst);
    d2[tid * 2] = p01;
    d2[tid * 2 + 1] = p23;
}

// ---------------- fused score + last-block softmax/agg ----------------
static __device__ __forceinline__ unsigned long long f2add(unsigned long long a, unsigned long long b){
    unsigned long long r; asm("add.rn.f32x2 %0, %1, %2;" : "=l"(r) : "l"(a), "l"(b)); return r;
}
static __device__ __forceinline__ unsigned long long f2fma(unsigned long long a, unsigned long long b, unsigned long long c){
    unsigned long long r; asm("fma.rn.f32x2 %0, %1, %2, %3;" : "=l"(r) : "l"(a), "l"(b), "l"(c)); return r;
}
static __device__ __forceinline__ float2 upk2(unsigned long long v){
    float2 f; asm("mov.b64 {%0, %1}, %2;" : "=f"(f.x), "=f"(f.y) : "l"(v)); return f;
}

#define OFF_HI  0
#define OFF_HT  (R_ * SHI_S)                  // 18576
#define OFF_W2  (OFF_HT + ET * D_)            // 22672
#define OFF_RED (OFF_W2 + D_)                 // 23184
#define OFF_UR  (OFF_RED + ET * STH)          // 25744
#define OFF_TE  (OFF_UR + R_)                 // 25780
#define SCORE_SMEM ((OFF_TE + ET) * 4)        // 103152 bytes

__global__ __launch_bounds__(STH) void score_k(const float* __restrict__ W2,
                                               const float* __restrict__ b2p,
                                               float* __restrict__ out)
{
    extern __shared__ float smf[];
    const int b = blockIdx.x, e0 = blockIdx.y * ET;
    const int tid = threadIdx.x;

    pdl_wait();

    {
        const float4* src  = reinterpret_cast<const float4*>(g_HI  + (size_t)b * R_ * D_);
        const float4* src2 = reinterpret_cast<const float4*>(g_HI2 + (size_t)b * R_ * D_);
        for (int i = tid; i < R_ * (D_ / 4); i += STH) {
            int row = i >> 7, c = i & 127;
            float4 a = src[i], d = src2[i];
            float4 o; o.x = a.x + d.x; o.y = a.y + d.y; o.z = a.z + d.z; o.w = a.w + d.w;
            reinterpret_cast<float4*>(smf + OFF_HI + row * SHI_S)[c] = o;
        }
        const float4* srcT  = reinterpret_cast<const float4*>(g_HT  + (size_t)(b * E_ + e0) * D_);
        const float4* srcT2 = reinterpret_cast<const float4*>(g_HT2 + (size_t)(b * E_ + e0) * D_);
        for (int i = tid; i < ET * (D_ / 4); i += STH) {
            float4 a = srcT[i], d = srcT2[i];
            float4 o; o.x = a.x + d.x; o.y = a.y + d.y; o.z = a.z + d.z; o.w = a.w + d.w;
            reinterpret_cast<float4*>(smf + OFF_HT)[i] = o;
        }
        const float4* srcW = reinterpret_cast<const float4*>(W2);
        for (int i = tid; i < D_ / 4; i += STH)
            reinterpret_cast<float4*>(smf + OFF_W2)[i] = srcW[i];
        if (tid < R_) {
            int r = b * R_ + tid;
            float s = 0.f;
            #pragma unroll
            for (int k = 0; k < 8; ++k) s += g_urp[k * IROWS_P + r];
            smf[OFF_UR + tid] = s;
        }
        if (tid < ET) {
            int r = b * E_ + e0 + tid;
            float s = 0.f;
            #pragma unroll
            for (int k = 0; k < 8; ++k) s += g_tep[k * TROWS + r];
            smf[OFF_TE + tid] = s;
        }
    }
    __syncthreads();

    int q8 = tid / 36;
    int r  = tid - q8 * 36;
    int q  = q8 < 7 ? q8 : 7;
    if (q8 > 7) r = tid - 8 * 36;

    const ulonglong2* hp = reinterpret_cast<const ulonglong2*>(smf + OFF_HI + r * SHI_S + q * 64);
    const ulonglong2* wp = reinterpret_cast<const ulonglong2*>(smf + OFF_W2 + q * 64);
    const ulonglong2* tp = reinterpret_cast<const ulonglong2*>(smf + OFF_HT + q * 64);

    const unsigned long long ABSM = 0x7FFFFFFF7FFFFFFFull;
    unsigned long long ac[ET];
    #pragma unroll
    for (int e = 0; e < ET; ++e) ac[e] = 0;

    #pragma unroll 4
    for (int j = 0; j < 16; ++j) {
        ulonglong2 h = hp[j];
        ulonglong2 w = wp[j];
        #pragma unroll
        for (int e = 0; e < ET; ++e) {
            ulonglong2 t = tp[e * 128 + j];
            ac[e] = f2fma(f2add(t.x, h.x) & ABSM, w.x, ac[e]);
            ac[e] = f2fma(f2add(t.y, h.y) & ABSM, w.y, ac[e]);
        }
    }

    #pragma unroll
    for (int e = 0; e < ET; ++e) {
        float2 p = upk2(ac[e]);
        smf[OFF_RED + e * STH + tid] = p.x + p.y;
    }
    __syncthreads();

    if (tid < R_) {
        float b2v = b2p[0];
        float ur  = smf[OFF_UR + tid];
        #pragma unroll
        for (int e = 0; e < ET; ++e) {
            const float* rd = smf + OFF_RED + e * STH;
            float S = 0.f;
            #pragma unroll
            for (int k = 0; k < 8; ++k) S += rd[k * 36 + tid];
            float raw = 0.5f * (smf[OFF_TE + e] + ur + S) + b2v;
            out[b * (E_ * R_) + (e0 + e) * R_ + tid] = 1.0f / (1.0f + expf(-raw));
        }
    }

    // ------- last-block ticket: softmax + aggregation for this batch -------
    __threadfence();
    __shared__ int ticket;
    __syncthreads();
    if (tid == 0) ticket = atomicAdd(&g_cnt[b], 1);
    __syncthreads();
    if (ticket != (E_ / ET) - 1) return;
    if (tid == 0) g_cnt[b] = 0;

    float* s   = smf;
    float* red = smf + E_ * R_;
    float* wr  = red + 16;
    const int lane = tid & 31, w = tid >> 5;

    float mx = -1e30f;
    for (int i = tid; i < E_ * R_; i += STH) {
        float v = out[b * E_ * R_ + i];
        s[i] = v;
        mx = fmaxf(mx, v);
    }
    #pragma unroll
    for (int o = 16; o; o >>= 1) mx = fmaxf(mx, __shfl_xor_sync(0xffffffffu, mx, o));
    if (lane == 0) red[w] = mx;
    __syncthreads();
    float m = red[0];
    #pragma unroll
    for (int k = 1; k < 10; ++k) m = fmaxf(m, red[k]);
    __syncthreads();

    float sum = 0.f;
    for (int i = tid; i < E_ * R_; i += STH) {
        float e2 = expf(s[i] - m);
        s[i] = e2;
        sum += e2;
    }
    #pragma unroll
    for (int o = 16; o; o >>= 1) sum += __shfl_xor_sync(0xffffffffu, sum, o);
    if (lane == 0) red[w] = sum;
    __syncthreads();
    float Z = 0.f;
    #pragma unroll
    for (int k = 0; k < 10; ++k) Z += red[k];
    float scale = 1.0f / (Z * (float)E_);

    if (tid < R_) {
        float a = 0.f;
        for (int e = 0; e < E_; ++e) a += s[e * R_ + tid];
        wr[tid] = a * scale;
    }
    __syncthreads();

    for (int d = tid; d < D_; d += STH) {
        float a = 0.f;
        #pragma unroll
        for (int r2 = 0; r2 < R_; ++r2)
            a += wr[r2] * g_I[(size_t)(b * R_ + r2) * D_ + d];
        out[B_ * E_ * R_ + b * D_ + d] = a;
    }
}

// ---------------- PDL launch helper ----------------
template <typename K, typename... Args>
static void launch_pdl(K kernel, dim3 grid, dim3 block, size_t smem, bool pdl, Args... args)
{
    cudaLaunchConfig_t cfg = {};
    cfg.gridDim = grid;
    cfg.blockDim = block;
    cfg.dynamicSmemBytes = smem;
    cudaLaunchAttribute attr[1];
    if (pdl) {
        attr[0].id = cudaLaunchAttributeProgrammaticStreamSerialization;
        attr[0].val.programmaticStreamSerializationAllowed = 1;
        cfg.attrs = attr;
        cfg.numAttrs = 1;
    }
    cudaLaunchKernelEx(&cfg, kernel, args...);
}

// ---------------- launch ----------------
extern "C" void kernel_launch(void* const* d_in, const int* in_sizes, int n_in,
                              void* d_out, int out_size)
{
    (void)in_sizes; (void)n_in; (void)out_size;
    const float* text      = (const float*)d_in[0];
    const float* image     = (const float*)d_in[1];
    const float* W_text    = (const float*)d_in[2];
    const float* b_text    = (const float*)d_in[3];
    const float* g_text    = (const float*)d_in[4];
    const float* beta_text = (const float*)d_in[5];
    const float* W_img     = (const float*)d_in[6];
    const float* b_img     = (const float*)d_in[7];
    const float* g_img     = (const float*)d_in[8];
    const float* beta_img  = (const float*)d_in[9];
    const float* W1        = (const float*)d_in[10];
    const float* b1        = (const float*)d_in[11];
    const float* W2        = (const float*)d_in[12];
    const float* b2        = (const float*)d_in[13];
    float* out = (float*)d_out;

    void* p;
    cudaGetSymbolAddress(&p, g_T);   float* T   = (float*)p;
    cudaGetSymbolAddress(&p, g_T2);  float* T2  = (float*)p;
    cudaGetSymbolAddress(&p, g_I);   float* I   = (float*)p;
    cudaGetSymbolAddress(&p, g_I2);  float* I2  = (float*)p;
    cudaGetSymbolAddress(&p, g_I3);  float* I3  = (float*)p;
    cudaGetSymbolAddress(&p, g_I4);  float* I4  = (float*)p;
    cudaGetSymbolAddress(&p, g_HT);  float* HT  = (float*)p;
    cudaGetSymbolAddress(&p, g_HT2); float* HT2 = (float*)p;
    cudaGetSymbolAddress(&p, g_HI);  float* HI  = (float*)p;
    cudaGetSymbolAddress(&p, g_HI2); float* HI2 = (float*)p;
    cudaGetSymbolAddress(&p, g_tep); float* tep = (float*)p;
    cudaGetSymbolAddress(&p, g_urp); float* urp = (float*)p;
    cudaGetSymbolAddress(&p, g_At);  __half* At  = (__half*)p;
    cudaGetSymbolAddress(&p, g_Ai);  __half* Ai  = (__half*)p;
    cudaGetSymbolAddress(&p, g_AT2); __half* AT2 = (__half*)p;
    cudaGetSymbolAddress(&p, g_AI2); __half* AI2 = (__half*)p;
    cudaGetSymbolAddress(&p, g_Bt);  __half* Bt  = (__half*)p;
    cudaGetSymbolAddress(&p, g_Bi);  __half* Bi  = (__half*)p;
    cudaGetSymbolAddress(&p, g_B1t); __half* B1t = (__half*)p;
    cudaGetSymbolAddress(&p, g_B1i); __half* B1i = (__half*)p;

    cudaFuncSetAttribute(mma_gemm3, cudaFuncAttributeMaxDynamicSharedMemorySize, SM_TOT);
    cudaFuncSetAttribute(score_k,   cudaFuncAttributeMaxDynamicSharedMemorySize, SCORE_SMEM);

    // conversions
    launch_pdl(conv_all_k, dim3(1920 + (TROWS*DT_ + IROWS*DI_)/1024), dim3(256), 0, false,
               W_text, W_img, W1, text, image);

    // phase A: text split-K 2-way + image split-K 4-way
    {
        JobPack P;
        P.j[0] = { At, Bt, b_text,  T,  nullptr, nullptr, DT_, DT_, 0,    384/32, TROWS,   0, 1 };
        P.j[1] = { At, Bt, nullptr, T2, nullptr, nullptr, DT_, DT_, 384,  384/32, TROWS,   0, 0 };
        P.j[2] = { Ai, Bi, b_img,   I,  nullptr, nullptr, DI_, DI_, 0,    512/32, IROWS_P, 0, 1 };
        P.j[3] = { Ai, Bi, nullptr, I2, nullptr, nullptr, DI_, DI_, 512,  512/32, IROWS_P, 0, 0 };
        P.j[4] = { Ai, Bi, nullptr, I3, nullptr, nullptr, DI_, DI_, 1024, 512/32, IROWS_P, 0, 0 };
        P.j[5] = { Ai, Bi, nullptr, I4, nullptr, nullptr, DI_, DI_, 1536, 512/32, IROWS_P, 0, 0 };
        P.hi[0] = 32; P.hi[1] = 64; P.hi[2] = 84; P.hi[3] = 104; P.hi[4] = 124; P.hi[5] = 144;
        launch_pdl(mma_gemm3, dim3(144), dim3(512), SM_TOT, true, P);
    }

    // merged LN (sums partials + relu) + fp16 convert
    launch_pdl(ln_all_k, dim3(TROWS + IROWS), dim3(128), 0, true,
               g_text, beta_text, g_img, beta_img);

    // phase B: split-K 2-way each, fused per-row W2 dot
    {
        JobPack P;
        P.j[0] = { AT2, B1t, nullptr, HT,  W2, tep,             D_, D_, 0,   256/32, TROWS,   0, 0 };
        P.j[1] = { AT2, B1t, nullptr, HT2, W2, tep + 4*TROWS,   D_, D_, 256, 256/32, TROWS,   0, 0 };
        P.j[2] = { AI2, B1i, b1,      HI,  W2, urp,             D_, D_, 0,   256/32, IROWS_P, 0, 1 };
        P.j[3] = { AI2, B1i, nullptr, HI2, W2, urp + 4*IROWS_P, D_, D_, 256, 256/32, IROWS_P, 0, 0 };
        P.j[4] = P.j[3]; P.j[5] = P.j[3];
        P.hi[0] = 32; P.hi[1] = 64; P.hi[2] = 84; P.hi[3] = 104; P.hi[4] = 104; P.hi[5] = 104;
        launch_pdl(mma_gemm3, dim3(104), dim3(512), SM_TOT, true, P);
    }

    // fused score + per-batch softmax/aggregation (last-block ticket)
    launch_pdl(score_k, dim3(B_, E_/ET), dim3(STH), SCORE_SMEM, true, W2, b2, out);
}